// round 16
// baseline (speedup 1.0000x reference)
#include <cuda_runtime.h>

#define NMAX 100000
#define EMAX 600000
#define FMAX 128

// Scratch (static device globals; no runtime allocation allowed)
__device__ float g_bufA[NMAX * FMAX];
__device__ float g_bufB[NMAX * FMAX];
__device__ float g_dinv[NMAX];
__device__ float g_stats[2 * FMAX];   // sum[128], sumsq[128] (reset by bn_final)
__device__ float g_scale[FMAX];
__device__ float g_shift[FMAX];
__device__ float g_pool[16 * FMAX];
__device__ int g_cnt[NMAX];
__device__ int g_rowptr[NMAX + 1];
__device__ int g_cursor[NMAX];
__device__ int g_srcs[EMAX];
__device__ int g_bsum[1024];

static inline int ceil_div(int a, int b) { return (a + b - 1) / b; }

// ---------------- setup: zero cnt + stats + pooled in one launch ----------------
__global__ void setup_kernel(int* cnt, float* stats, float* pooled, int n) {
    int i = blockIdx.x * blockDim.x + threadIdx.x;
    if (i < n) cnt[i] = 0;
    if (i < 256) stats[i] = 0.f;
    if (i < 16 * 128) pooled[i] = 0.f;
}

// ---------------- CSR build: counting sort of edges by dst ----------------
__global__ void hist_kernel(int* cnt, const int* __restrict__ dst, int E) {
    int e = blockIdx.x * blockDim.x + threadIdx.x;
    if (e < E) atomicAdd(&cnt[dst[e]], 1);
}

__global__ void scan1_kernel(const int* __restrict__ cnt, int* rowptr, int* bsum, int n) {
    __shared__ int sm[256];
    int tid = threadIdx.x;
    int gid = blockIdx.x * 256 + tid;
    int v = (gid < n) ? cnt[gid] : 0;
    sm[tid] = v;
    __syncthreads();
#pragma unroll
    for (int off = 1; off < 256; off <<= 1) {
        int t = (tid >= off) ? sm[tid - off] : 0;
        __syncthreads();
        sm[tid] += t;
        __syncthreads();
    }
    if (gid < n) rowptr[gid] = sm[tid] - v;  // exclusive within block
    if (tid == 255) bsum[blockIdx.x] = sm[255];
}

// scan3 with the inter-block offset computed in-kernel (masked reduction over bsum)
__global__ void scan3_kernel(int* rowptr, const int* __restrict__ bsum, int* cursor,
                             const int* __restrict__ cnt, float* dinv,
                             int n, int E, int nb) {
    __shared__ int sm[512];
    int t = threadIdx.x;  // 0..511
    sm[t] = (t < nb && t < blockIdx.x) ? bsum[t] : 0;
    __syncthreads();
#pragma unroll
    for (int off = 256; off > 0; off >>= 1) {
        if (t < off) sm[t] += sm[t + off];
        __syncthreads();
    }
    int exoff = sm[0];
    if (t < 256) {
        int gid = blockIdx.x * 256 + t;
        if (gid < n) {
            int r = rowptr[gid] + exoff;
            rowptr[gid] = r;
            cursor[gid] = r;
            dinv[gid] = rsqrtf((float)(cnt[gid] + 1));  // +1 self-loop
        }
        if (gid == 0) rowptr[n] = E;
    }
}

__global__ void reorder_kernel(const int* __restrict__ src, const int* __restrict__ dst,
                               int* cursor, int* srcs, int E) {
    int e = blockIdx.x * blockDim.x + threadIdx.x;
    if (e < E) {
        int p = atomicAdd(&cursor[dst[e]], 1);
        srcs[p] = src[e];
    }
}

// ---- layer 1: pull(C=3) + X@W1 (3->64) + fused BN statistics ----
__global__ void pull3_k3_kernel(const float* __restrict__ pos, const float* __restrict__ w1,
                                const float* __restrict__ dinv,
                                const int* __restrict__ rowptr, const int* __restrict__ srcs,
                                float* __restrict__ y, int n,
                                float* gsum, float* gsq) {
    __shared__ float w1s[192];  // [3][64]
    __shared__ float sS[64], sQ[64];
    int tid = threadIdx.x;
    if (tid < 192) w1s[tid] = w1[tid];
    if (tid < 64) { sS[tid] = 0.f; sQ[tid] = 0.f; }
    __syncthreads();
    int v = blockIdx.x * blockDim.x + tid;
    if (v < n) {
        float di = dinv[v];
        float dd = di * di;
        float a0 = dd * pos[v * 3 + 0];
        float a1 = dd * pos[v * 3 + 1];
        float a2 = dd * pos[v * 3 + 2];
        int e1 = rowptr[v + 1];
        for (int e = rowptr[v]; e < e1; e++) {
            int s = __ldg(&srcs[e]);
            float nrm = di * __ldg(&dinv[s]);
            a0 = fmaf(nrm, __ldg(&pos[s * 3 + 0]), a0);
            a1 = fmaf(nrm, __ldg(&pos[s * 3 + 1]), a1);
            a2 = fmaf(nrm, __ldg(&pos[s * 3 + 2]), a2);
        }
        float4* y4 = (float4*)(y + v * 64);
#pragma unroll
        for (int c4 = 0; c4 < 16; c4++) {
            float4 o;
            int c = c4 * 4;
            o.x = a0 * w1s[c + 0] + a1 * w1s[64 + c + 0] + a2 * w1s[128 + c + 0];
            o.y = a0 * w1s[c + 1] + a1 * w1s[64 + c + 1] + a2 * w1s[128 + c + 1];
            o.z = a0 * w1s[c + 2] + a1 * w1s[64 + c + 2] + a2 * w1s[128 + c + 2];
            o.w = a0 * w1s[c + 3] + a1 * w1s[64 + c + 3] + a2 * w1s[128 + c + 3];
            y4[c4] = o;
        }
    }
    __syncthreads();
    // fused BN statistics: re-read the block's tile (L2-hot)
    {
        int c = tid & 63;
        int rg = tid >> 6;  // 0..3
        int base = blockIdx.x * 256 + rg * 64;
        float s = 0.f, q = 0.f;
#pragma unroll 4
        for (int i = 0; i < 64; i++) {
            int r = base + i;
            if (r < n) {
                float val = y[r * 64 + c];
                s += val;
                q = fmaf(val, val, q);
            }
        }
        atomicAdd(&sS[c], s);
        atomicAdd(&sQ[c], q);
    }
    __syncthreads();
    if (tid < 64) {
        atomicAdd(&gsum[tid], sS[tid]);
        atomicAdd(&gsq[tid], sQ[tid]);
    }
}

// compute scale/shift; zero pad channels; reset stats for the next layer
__global__ void bn_final_kernel(float* gsum, float* gsq,
                                const float* __restrict__ gamma, const float* __restrict__ beta,
                                float* scale, float* shift, int n, int C) {
    int c = threadIdx.x;  // 128
    float sc = 0.f, sh = 0.f;
    if (c < C) {
        float inv_n = 1.0f / (float)n;
        float m = gsum[c] * inv_n;
        float var = gsq[c] * inv_n - m * m;
        float rs = rsqrtf(var + 1e-5f);
        sc = gamma[c] * rs;
        sh = beta[c] - m * sc;
    }
    scale[c] = sc;
    shift[c] = sh;
    gsum[c] = 0.f;
    gsq[c] = 0.f;
}

// ---------------- pull-aggregate with fused BN+relu on the source ----------------
__device__ __forceinline__ float4 bn4(float4 v, float4 sc, float4 sh) {
    float4 r;
    r.x = fmaxf(fmaf(v.x, sc.x, sh.x), 0.f);
    r.y = fmaxf(fmaf(v.y, sc.y, sh.y), 0.f);
    r.z = fmaxf(fmaf(v.z, sc.z, sh.z), 0.f);
    r.w = fmaxf(fmaf(v.w, sc.w, sh.w), 0.f);
    return r;
}

__device__ __forceinline__ void fma4(float4& acc, float nn, const float4& v) {
    acc.x = fmaf(nn, v.x, acc.x);
    acc.y = fmaf(nn, v.y, acc.y);
    acc.z = fmaf(nn, v.z, acc.z);
    acc.w = fmaf(nn, v.w, acc.w);
}

// layer-2 variant: ld4=16, G=8 lanes x 2 float4 each (R13-proven 2-unroll)
__global__ void pull_bn64_kernel(const float* __restrict__ x, float* __restrict__ agg,
                                 const float* __restrict__ dinv,
                                 const int* __restrict__ rowptr, const int* __restrict__ srcs,
                                 const float* __restrict__ scale, const float* __restrict__ shift,
                                 int n) {
    int group = (blockIdx.x * blockDim.x + threadIdx.x) >> 3;
    int lane = threadIdx.x & 7;
    if (group >= n) return;
    const float4* sc4 = (const float4*)scale;
    const float4* sh4 = (const float4*)shift;
    float4 sc0 = sc4[lane], sc1 = sc4[lane + 8];
    float4 sh0 = sh4[lane], sh1 = sh4[lane + 8];
    float di = dinv[group];
    const float4* x4 = (const float4*)x;
    int b = group * 16 + lane;
    float dd = di * di;
    float4 t0 = bn4(__ldg(&x4[b]), sc0, sh0);
    float4 t1 = bn4(__ldg(&x4[b + 8]), sc1, sh1);
    float4 acc0 = make_float4(dd * t0.x, dd * t0.y, dd * t0.z, dd * t0.w);
    float4 acc1 = make_float4(dd * t1.x, dd * t1.y, dd * t1.z, dd * t1.w);
    int e = rowptr[group];
    int e1 = rowptr[group + 1];
    for (; e + 1 < e1; e += 2) {
        int s0 = __ldg(&srcs[e]);
        int s1 = __ldg(&srcs[e + 1]);
        float n0 = di * __ldg(&dinv[s0]);
        float n1 = di * __ldg(&dinv[s1]);
        int p0 = s0 * 16 + lane, p1 = s1 * 16 + lane;
        float4 u0 = __ldg(&x4[p0]);
        float4 u1 = __ldg(&x4[p0 + 8]);
        float4 v0 = __ldg(&x4[p1]);
        float4 v1 = __ldg(&x4[p1 + 8]);
        fma4(acc0, n0, bn4(u0, sc0, sh0));
        fma4(acc1, n0, bn4(u1, sc1, sh1));
        fma4(acc0, n1, bn4(v0, sc0, sh0));
        fma4(acc1, n1, bn4(v1, sc1, sh1));
    }
    if (e < e1) {
        int s0 = __ldg(&srcs[e]);
        float n0 = di * __ldg(&dinv[s0]);
        int p0 = s0 * 16 + lane;
        fma4(acc0, n0, bn4(__ldg(&x4[p0]), sc0, sh0));
        fma4(acc1, n0, bn4(__ldg(&x4[p0 + 8]), sc1, sh1));
    }
    float4* o4 = (float4*)agg;
    o4[b] = acc0;
    o4[b + 8] = acc1;
}

// layer-3 variant: ld4=24, G=8 lanes x 3 float4 each (R13-proven 2-unroll)
__global__ void pull_bn96_kernel(const float* __restrict__ x, float* __restrict__ agg,
                                 const float* __restrict__ dinv,
                                 const int* __restrict__ rowptr, const int* __restrict__ srcs,
                                 const float* __restrict__ scale, const float* __restrict__ shift,
                                 int n) {
    int group = (blockIdx.x * blockDim.x + threadIdx.x) >> 3;
    int lane = threadIdx.x & 7;
    if (group >= n) return;
    const float4* sc4 = (const float4*)scale;
    const float4* sh4 = (const float4*)shift;
    float4 sc0 = sc4[lane], sc1 = sc4[lane + 8], sc2 = sc4[lane + 16];
    float4 sh0 = sh4[lane], sh1 = sh4[lane + 8], sh2 = sh4[lane + 16];
    float di = dinv[group];
    const float4* x4 = (const float4*)x;
    int b = group * 24 + lane;
    float dd = di * di;
    float4 t0 = bn4(__ldg(&x4[b]), sc0, sh0);
    float4 t1 = bn4(__ldg(&x4[b + 8]), sc1, sh1);
    float4 t2 = bn4(__ldg(&x4[b + 16]), sc2, sh2);
    float4 acc0 = make_float4(dd * t0.x, dd * t0.y, dd * t0.z, dd * t0.w);
    float4 acc1 = make_float4(dd * t1.x, dd * t1.y, dd * t1.z, dd * t1.w);
    float4 acc2 = make_float4(dd * t2.x, dd * t2.y, dd * t2.z, dd * t2.w);
    int e = rowptr[group];
    int e1 = rowptr[group + 1];
    for (; e + 1 < e1; e += 2) {
        int s0 = __ldg(&srcs[e]);
        int s1 = __ldg(&srcs[e + 1]);
        float n0 = di * __ldg(&dinv[s0]);
        float n1 = di * __ldg(&dinv[s1]);
        int p0 = s0 * 24 + lane, p1 = s1 * 24 + lane;
        float4 u0 = __ldg(&x4[p0]);
        float4 u1 = __ldg(&x4[p0 + 8]);
        float4 u2 = __ldg(&x4[p0 + 16]);
        float4 v0 = __ldg(&x4[p1]);
        float4 v1 = __ldg(&x4[p1 + 8]);
        float4 v2 = __ldg(&x4[p1 + 16]);
        fma4(acc0, n0, bn4(u0, sc0, sh0));
        fma4(acc1, n0, bn4(u1, sc1, sh1));
        fma4(acc2, n0, bn4(u2, sc2, sh2));
        fma4(acc0, n1, bn4(v0, sc0, sh0));
        fma4(acc1, n1, bn4(v1, sc1, sh1));
        fma4(acc2, n1, bn4(v2, sc2, sh2));
    }
    if (e < e1) {
        int s0 = __ldg(&srcs[e]);
        float n0 = di * __ldg(&dinv[s0]);
        int p0 = s0 * 24 + lane;
        fma4(acc0, n0, bn4(__ldg(&x4[p0]), sc0, sh0));
        fma4(acc1, n0, bn4(__ldg(&x4[p0 + 8]), sc1, sh1));
        fma4(acc2, n0, bn4(__ldg(&x4[p0 + 16]), sc2, sh2));
    }
    float4* o4 = (float4*)agg;
    o4[b] = acc0;
    o4[b + 8] = acc1;
    o4[b + 16] = acc2;
}

// ---------------- tf32 tensor-core GEMM with X register-prefetch ----------------
__device__ __forceinline__ unsigned f2tf32(float v) {
    unsigned u;
    asm("cvt.rna.tf32.f32 %0, %1;" : "=r"(u) : "f"(v));
    return u;
}

#define MMA_TF32(d, A, B)                                              \
    asm volatile(                                                      \
        "mma.sync.aligned.m16n8k8.row.col.f32.tf32.tf32.f32 "          \
        "{%0,%1,%2,%3}, {%4,%5,%6,%7}, {%8,%9}, {%0,%1,%2,%3};"        \
        : "+f"(d[0]), "+f"(d[1]), "+f"(d[2]), "+f"(d[3])               \
        : "r"(A.x), "r"(A.y), "r"(A.z), "r"(A.w), "r"(B.x), "r"(B.y))

template <int NT, int DOPOOL>  // NT: n8-tiles per warp (3->96 cols, 4->128 cols)
__global__ __launch_bounds__(256) void gemm_tf32_kernel(
    const float* __restrict__ X, const float* __restrict__ W,
    const float* __restrict__ bias, float* __restrict__ Y,
    int n, int K, int M, int ldX, int ldY, int doRelu,
    const float* __restrict__ bnScale, const float* __restrict__ bnShift,
    float* gsum, float* gsq,
    const int* __restrict__ batch, float* pooled) {
    const int COLS = NT * 32;
    __shared__ unsigned Xfrag[4 * 8 * 32 * 4];   // [ks][mt][lane][4]
    __shared__ unsigned Wfrag[4 * 16 * 32 * 2];  // [ks][ntGlobal][lane][2]
    __shared__ float sSum[DOPOOL ? 1 : 128], sSq[DOPOOL ? 1 : 128];
    __shared__ float spool[DOPOOL ? 16 * 128 : 1];

    int tid = threadIdx.x;
    int lane = tid & 31;
    int wid = tid >> 5;
    int warpM = wid >> 2;  // 0..1
    int warpN = wid & 3;   // 0..3
    int row0 = blockIdx.x * 128;
    int g = lane >> 2, tig = lane & 3;

    // X staging geometry: warp w stages rows rowb+8u (u=0..15), column kk.
    // Fragment index closed form (identical addresses to the proven scalar path):
    int kk = tid & 31;
    int rowb = tid >> 5;  // 0..7
    {
    }
    int ttX = kk & 3, ksX = kk >> 3, jX = (kk >> 2) & 1;
    unsigned xbase = (unsigned)((ksX << 10) + ((rowb << 2) + ttX) * 4 + 2 * jX);

    float acc[4][NT][4];
#pragma unroll
    for (int mt = 0; mt < 4; mt++)
#pragma unroll
        for (int nt = 0; nt < NT; nt++)
#pragma unroll
            for (int r = 0; r < 4; r++) acc[mt][nt][r] = 0.f;

    if (!DOPOOL) {
        if (gsum && tid < 128) { sSum[tid] = 0.f; sSq[tid] = 0.f; }
    } else {
        for (int i = tid; i < 16 * 128; i += 256) spool[i] = 0.f;
    }

    // ---- prologue: stage chunk 0 (X direct + W) ----
    {
        int kg = kk;  // k0 = 0; kg < K always (K >= 64)
        float bs = 0.f, bh = 0.f;
        if (bnScale) { bs = bnScale[kg]; bh = bnShift[kg]; }
#pragma unroll
        for (int u = 0; u < 16; u++) {
            int gr = row0 + rowb + 8 * u;
            float v = 0.f;
            if (gr < n) {
                v = X[gr * ldX + kg];
                if (bnScale) v = fmaxf(fmaf(v, bs, bh), 0.f);
            }
            Xfrag[xbase + ((u >> 1) << 7) + (u & 1)] = f2tf32(v);
        }
        for (int t = tid; t < 32 * COLS; t += 256) {
            int kkw = t / COLS, cc = t - kkw * COLS;
            float v = (kkw < K && cc < M) ? W[kkw * M + cc] : 0.f;
            int ttw = kkw & 3, ksw = kkw >> 3, jw = (kkw >> 2) & 1;
            int nt = cc >> 3, gn = cc & 7;
            Wfrag[(((ksw << 4) + nt) << 6) + ((gn << 2) + ttw) * 2 + jw] = f2tf32(v);
        }
    }
    __syncthreads();

    int nChunks = (K + 31) >> 5;
    for (int c = 0; c < nChunks; c++) {
        int k0 = c << 5;
        bool hasNext = (c + 1 < nChunks);
        // prefetch next X chunk into registers (LDGs overlap the MMAs below)
        float xpre[16];
        if (hasNext) {
            int kgn = k0 + 32 + kk;
            bool kok = kgn < K;
            float bs = 0.f, bh = 0.f;
            if (bnScale && kok) { bs = bnScale[kgn]; bh = bnShift[kgn]; }
#pragma unroll
            for (int u = 0; u < 16; u++) {
                int gr = row0 + rowb + 8 * u;
                float v = 0.f;
                if (gr < n && kok) {
                    v = X[gr * ldX + kgn];
                    if (bnScale) v = fmaxf(fmaf(v, bs, bh), 0.f);
                }
                xpre[u] = v;
            }
        }
        // MMAs on current smem chunk
#pragma unroll
        for (int ks = 0; ks < 4; ks++) {
            uint4 a[4];
            uint2 b[NT];
#pragma unroll
            for (int mt = 0; mt < 4; mt++)
                a[mt] = *(const uint4*)&Xfrag[(((ks << 3) + (warpM << 2) + mt) << 7) + (lane << 2)];
#pragma unroll
            for (int nt = 0; nt < NT; nt++)
                b[nt] = *(const uint2*)&Wfrag[(((ks << 4) + warpN * NT + nt) << 6) + (lane << 1)];
#pragma unroll
            for (int mt = 0; mt < 4; mt++)
#pragma unroll
                for (int nt = 0; nt < NT; nt++) MMA_TF32(acc[mt][nt], a[mt], b[nt]);
        }
        if (hasNext) {
            __syncthreads();
            // commit prefetched X; stage next W (small, L2-hot)
#pragma unroll
            for (int u = 0; u < 16; u++)
                Xfrag[xbase + ((u >> 1) << 7) + (u & 1)] = f2tf32(xpre[u]);
            int k0n = k0 + 32;
            for (int t = tid; t < 32 * COLS; t += 256) {
                int kkw = t / COLS, cc = t - kkw * COLS;
                int kg = k0n + kkw;
                float v = (kg < K && cc < M) ? W[kg * M + cc] : 0.f;
                int ttw = kkw & 3, ksw = kkw >> 3, jw = (kkw >> 2) & 1;
                int nt = cc >> 3, gn = cc & 7;
                Wfrag[(((ksw << 4) + nt) << 6) + ((gn << 2) + ttw) * 2 + jw] = f2tf32(v);
            }
            __syncthreads();
        }
    }

    if (!DOPOOL) {
        // fused BN statistics (pre-activation); padded rows/cols are exact zeros
        if (gsum) {
#pragma unroll
            for (int nt = 0; nt < NT; nt++) {
                int cb = (warpN * NT + nt) * 8 + tig * 2;
                float s0 = 0.f, q0 = 0.f, s1 = 0.f, q1 = 0.f;
#pragma unroll
                for (int mt = 0; mt < 4; mt++) {
                    float v0 = acc[mt][nt][0], v2 = acc[mt][nt][2];
                    float v1 = acc[mt][nt][1], v3 = acc[mt][nt][3];
                    s0 += v0 + v2; q0 += v0 * v0 + v2 * v2;
                    s1 += v1 + v3; q1 += v1 * v1 + v3 * v3;
                }
                atomicAdd(&sSum[cb], s0);
                atomicAdd(&sSq[cb], q0);
                atomicAdd(&sSum[cb + 1], s1);
                atomicAdd(&sSq[cb + 1], q1);
            }
            __syncthreads();
            if (tid < 128) {
                atomicAdd(&gsum[tid], sSum[tid]);
                atomicAdd(&gsq[tid], sSq[tid]);
            }
        }
        // store
#pragma unroll
        for (int mt = 0; mt < 4; mt++) {
            int rbase = row0 + warpM * 64 + mt * 16 + g;
#pragma unroll
            for (int nt = 0; nt < NT; nt++) {
                int cb = (warpN * NT + nt) * 8 + tig * 2;
                if (cb >= ldY) continue;
                float bb0 = 0.f, bb1 = 0.f;
                if (bias) {
                    if (cb < M) bb0 = bias[cb];
                    if (cb + 1 < M) bb1 = bias[cb + 1];
                }
#pragma unroll
                for (int h = 0; h < 2; h++) {
                    int r = rbase + h * 8;
                    if (r >= n) continue;
                    float v0 = acc[mt][nt][2 * h] + bb0;
                    float v1 = acc[mt][nt][2 * h + 1] + bb1;
                    if (doRelu) { v0 = fmaxf(v0, 0.f); v1 = fmaxf(v1, 0.f); }
                    if (cb >= M) v0 = 0.f;      // pad column -> keep zero
                    if (cb + 1 >= M) v1 = 0.f;
                    *(float2*)&Y[r * ldY + cb] = make_float2(v0, v1);
                }
            }
        }
    } else {
        // fused global-sum-pool: relu(v + bias) accumulated per graph
#pragma unroll
        for (int mt = 0; mt < 4; mt++) {
            int rbase = row0 + warpM * 64 + mt * 16 + g;
#pragma unroll
            for (int nt = 0; nt < NT; nt++) {
                int cb = (warpN * NT + nt) * 8 + tig * 2;
                float bb0 = (cb < M) ? bias[cb] : 0.f;
                float bb1 = (cb + 1 < M) ? bias[cb + 1] : 0.f;
#pragma unroll
                for (int h = 0; h < 2; h++) {
                    int r = rbase + h * 8;
                    if (r >= n) continue;
                    int gb = __ldg(&batch[r]);
                    float v0 = fmaxf(acc[mt][nt][2 * h] + bb0, 0.f);
                    float v1 = fmaxf(acc[mt][nt][2 * h + 1] + bb1, 0.f);
                    atomicAdd(&spool[gb * 128 + cb], v0);
                    atomicAdd(&spool[gb * 128 + cb + 1], v1);
                }
            }
        }
        __syncthreads();
        int rlast = min(row0 + 127, n - 1);
        if (row0 < n) {
            int gmin = __ldg(&batch[row0]);
            int gmax = __ldg(&batch[rlast]);
            if (tid < 128) {
                for (int gg2 = gmin; gg2 <= gmax; gg2++)
                    atomicAdd(&pooled[gg2 * 128 + tid], spool[gg2 * 128 + tid]);
            }
        }
    }
}

// ---------------- MLP head on [16,128] ----------------
__global__ void head_kernel(const float* __restrict__ pooled,
                            const float* __restrict__ fw1, const float* __restrict__ fb1,
                            const float* __restrict__ fw2, const float* __restrict__ fb2,
                            const float* __restrict__ fw3, const float* __restrict__ fb3,
                            float* __restrict__ out) {
    __shared__ float s0[128], s1[128], s2[128];
    int t = threadIdx.x;
    int g = blockIdx.x;
    s0[t] = pooled[g * 128 + t];
    __syncthreads();
    float a = fb1[t];
    for (int k = 0; k < 128; k++) a = fmaf(s0[k], fw1[k * 128 + t], a);
    s1[t] = fmaxf(a, 0.f);
    __syncthreads();
    a = fb2[t];
    for (int k = 0; k < 128; k++) a = fmaf(s1[k], fw2[k * 128 + t], a);
    s2[t] = fmaxf(a, 0.f);
    __syncthreads();
    if (t < 100) {
        a = fb3[t];
        for (int k = 0; k < 128; k++) a = fmaf(s2[k], fw3[k * 100 + t], a);
        out[g * 100 + t] = a;
    }
}

// ---------------- launcher ----------------
extern "C" void kernel_launch(void* const* d_in, const int* in_sizes, int n_in,
                              void* d_out, int out_size) {
    const float* pos = (const float*)d_in[0];
    const int* ei = (const int*)d_in[1];     // int32
    const int* batch = (const int*)d_in[2];  // int32
    const float* w1 = (const float*)d_in[3];
    // d_in[4] = b1: cancels in BatchNorm (mean subtraction) -> skipped
    const float* g1 = (const float*)d_in[5];
    const float* be1 = (const float*)d_in[6];
    const float* w2 = (const float*)d_in[7];
    const float* g2 = (const float*)d_in[9];
    const float* be2 = (const float*)d_in[10];
    const float* w3 = (const float*)d_in[11];
    const float* g3 = (const float*)d_in[13];
    const float* be3 = (const float*)d_in[14];
    const float* fw0 = (const float*)d_in[15];
    const float* fb0 = (const float*)d_in[16];
    const float* fw1 = (const float*)d_in[17];
    const float* fb1 = (const float*)d_in[18];
    const float* fw2 = (const float*)d_in[19];
    const float* fb2 = (const float*)d_in[20];
    const float* fw3 = (const float*)d_in[21];
    const float* fb3 = (const float*)d_in[22];

    int n = in_sizes[2];       // N
    int E = in_sizes[1] / 2;   // directed edges
    const int* src = ei;
    const int* dst = ei + E;

    float *A, *B, *dinv, *stats, *scale, *shift, *pooled;
    int *cnt, *rowptr, *cursor, *srcs, *bsum;
    cudaGetSymbolAddress((void**)&A, g_bufA);
    cudaGetSymbolAddress((void**)&B, g_bufB);
    cudaGetSymbolAddress((void**)&dinv, g_dinv);
    cudaGetSymbolAddress((void**)&stats, g_stats);
    cudaGetSymbolAddress((void**)&scale, g_scale);
    cudaGetSymbolAddress((void**)&shift, g_shift);
    cudaGetSymbolAddress((void**)&pooled, g_pool);
    cudaGetSymbolAddress((void**)&cnt, g_cnt);
    cudaGetSymbolAddress((void**)&rowptr, g_rowptr);
    cudaGetSymbolAddress((void**)&cursor, g_cursor);
    cudaGetSymbolAddress((void**)&srcs, g_srcs);
    cudaGetSymbolAddress((void**)&bsum, g_bsum);
    float* gsum = stats;
    float* gsq = stats + 128;

    const int T = 256;
    int nb = ceil_div(n, 256);
    int gemmBlocks = ceil_div(n, 128);

    // ---- setup + CSR build ----
    setup_kernel<<<ceil_div(n, T), T>>>(cnt, stats, pooled, n);
    hist_kernel<<<ceil_div(E, T), T>>>(cnt, dst, E);
    scan1_kernel<<<nb, 256>>>(cnt, rowptr, bsum, n);
    scan3_kernel<<<nb, 512>>>(rowptr, bsum, cursor, cnt, dinv, n, E, nb);
    reorder_kernel<<<ceil_div(E, T), T>>>(src, dst, cursor, srcs, E);

    // ---- layer 1: pull(C=3) + GEMM 3->64 + BN stats fused -> B (pre-BN); final ----
    pull3_k3_kernel<<<ceil_div(n, T), T>>>(pos, w1, dinv, rowptr, srcs, B, n, gsum, gsq);
    bn_final_kernel<<<1, 128>>>(gsum, gsq, g1, be1, scale, shift, n, 64);

    // ---- layer 2: pull(BN1 fused, G=8x2) -> A; tf32 GEMM 64->94 -> B + stats ----
    pull_bn64_kernel<<<ceil_div(n * 8, T), T>>>(B, A, dinv, rowptr, srcs, scale, shift, n);
    gemm_tf32_kernel<3, 0><<<gemmBlocks, 256>>>(A, w2, nullptr, B, n, 64, 94, 64, 96, 0,
                                                nullptr, nullptr, gsum, gsq,
                                                nullptr, nullptr);
    bn_final_kernel<<<1, 128>>>(gsum, gsq, g2, be2, scale, shift, n, 94);

    // ---- layer 3: pull(BN2 fused, G=8x3) -> A; tf32 GEMM 94->128 -> B + stats ----
    pull_bn96_kernel<<<ceil_div(n * 8, T), T>>>(B, A, dinv, rowptr, srcs, scale, shift, n);
    gemm_tf32_kernel<4, 0><<<gemmBlocks, 256>>>(A, w3, nullptr, B, n, 94, 128, 96, 128, 0,
                                                nullptr, nullptr, gsum, gsq,
                                                nullptr, nullptr);
    bn_final_kernel<<<1, 128>>>(gsum, gsq, g3, be3, scale, shift, n, 128);

    // ---- fw0: BN3+relu fused into X staging; +bias +relu; pool fused -> pooled ----
    gemm_tf32_kernel<4, 1><<<gemmBlocks, 256>>>(B, fw0, fb0, nullptr, n, 128, 128, 128, 128, 1,
                                                scale, shift, nullptr, nullptr,
                                                batch, pooled);

    // ---- head ----
    head_kernel<<<16, 128>>>(pooled, fw1, fb1, fw2, fb2, fw3, fb3, (float*)d_out);
}

// round 17
// speedup vs baseline: 1.2903x; 1.2903x over previous
#include <cuda_runtime.h>

#define NMAX 100000
#define EMAX 600000
#define FMAX 128

// Scratch (static device globals; no runtime allocation allowed)
__device__ float g_bufA[NMAX * FMAX];
__device__ float g_bufB[NMAX * FMAX];
__device__ float g_dinv[NMAX];
__device__ float g_stats[2 * FMAX];   // sum[128], sumsq[128] (reset by bn_final)
__device__ float g_scale[FMAX];
__device__ float g_shift[FMAX];
__device__ float g_pool[16 * FMAX];
__device__ int g_cnt[NMAX];
__device__ int g_rowptr[NMAX + 1];
__device__ int g_cursor[NMAX];
__device__ int g_srcs[EMAX];
__device__ int g_bsum[1024];

static inline int ceil_div(int a, int b) { return (a + b - 1) / b; }

// ---------------- setup: zero cnt + stats + pooled in one launch ----------------
__global__ void setup_kernel(int* cnt, float* stats, float* pooled, int n) {
    int i = blockIdx.x * blockDim.x + threadIdx.x;
    if (i < n) cnt[i] = 0;
    if (i < 256) stats[i] = 0.f;
    if (i < 16 * 128) pooled[i] = 0.f;
}

// ---------------- CSR build: counting sort of edges by dst ----------------
__global__ void hist_kernel(int* cnt, const int* __restrict__ dst, int E) {
    int e = blockIdx.x * blockDim.x + threadIdx.x;
    if (e < E) atomicAdd(&cnt[dst[e]], 1);
}

__global__ void scan1_kernel(const int* __restrict__ cnt, int* rowptr, int* bsum, int n) {
    __shared__ int sm[256];
    int tid = threadIdx.x;
    int gid = blockIdx.x * 256 + tid;
    int v = (gid < n) ? cnt[gid] : 0;
    sm[tid] = v;
    __syncthreads();
#pragma unroll
    for (int off = 1; off < 256; off <<= 1) {
        int t = (tid >= off) ? sm[tid - off] : 0;
        __syncthreads();
        sm[tid] += t;
        __syncthreads();
    }
    if (gid < n) rowptr[gid] = sm[tid] - v;  // exclusive within block
    if (tid == 255) bsum[blockIdx.x] = sm[255];
}

// scan3 with the inter-block offset computed in-kernel (masked reduction over bsum)
__global__ void scan3_kernel(int* rowptr, const int* __restrict__ bsum, int* cursor,
                             const int* __restrict__ cnt, float* dinv,
                             int n, int E, int nb) {
    __shared__ int sm[512];
    int t = threadIdx.x;  // 0..511
    sm[t] = (t < nb && t < blockIdx.x) ? bsum[t] : 0;
    __syncthreads();
#pragma unroll
    for (int off = 256; off > 0; off >>= 1) {
        if (t < off) sm[t] += sm[t + off];
        __syncthreads();
    }
    int exoff = sm[0];
    if (t < 256) {
        int gid = blockIdx.x * 256 + t;
        if (gid < n) {
            int r = rowptr[gid] + exoff;
            rowptr[gid] = r;
            cursor[gid] = r;
            dinv[gid] = rsqrtf((float)(cnt[gid] + 1));  // +1 self-loop
        }
        if (gid == 0) rowptr[n] = E;
    }
}

__global__ void reorder_kernel(const int* __restrict__ src, const int* __restrict__ dst,
                               int* cursor, int* srcs, int E) {
    int e = blockIdx.x * blockDim.x + threadIdx.x;
    if (e < E) {
        int p = atomicAdd(&cursor[dst[e]], 1);
        srcs[p] = src[e];
    }
}

// ---- layer 1: pull(C=3) + X@W1 (3->64) + fused BN statistics ----
__global__ void pull3_k3_kernel(const float* __restrict__ pos, const float* __restrict__ w1,
                                const float* __restrict__ dinv,
                                const int* __restrict__ rowptr, const int* __restrict__ srcs,
                                float* __restrict__ y, int n,
                                float* gsum, float* gsq) {
    __shared__ float w1s[192];  // [3][64]
    __shared__ float sS[64], sQ[64];
    int tid = threadIdx.x;
    if (tid < 192) w1s[tid] = w1[tid];
    if (tid < 64) { sS[tid] = 0.f; sQ[tid] = 0.f; }
    __syncthreads();
    int v = blockIdx.x * blockDim.x + tid;
    if (v < n) {
        float di = dinv[v];
        float dd = di * di;
        float a0 = dd * pos[v * 3 + 0];
        float a1 = dd * pos[v * 3 + 1];
        float a2 = dd * pos[v * 3 + 2];
        int e1 = rowptr[v + 1];
        for (int e = rowptr[v]; e < e1; e++) {
            int s = __ldg(&srcs[e]);
            float nrm = di * __ldg(&dinv[s]);
            a0 = fmaf(nrm, __ldg(&pos[s * 3 + 0]), a0);
            a1 = fmaf(nrm, __ldg(&pos[s * 3 + 1]), a1);
            a2 = fmaf(nrm, __ldg(&pos[s * 3 + 2]), a2);
        }
        float4* y4 = (float4*)(y + v * 64);
#pragma unroll
        for (int c4 = 0; c4 < 16; c4++) {
            float4 o;
            int c = c4 * 4;
            o.x = a0 * w1s[c + 0] + a1 * w1s[64 + c + 0] + a2 * w1s[128 + c + 0];
            o.y = a0 * w1s[c + 1] + a1 * w1s[64 + c + 1] + a2 * w1s[128 + c + 1];
            o.z = a0 * w1s[c + 2] + a1 * w1s[64 + c + 2] + a2 * w1s[128 + c + 2];
            o.w = a0 * w1s[c + 3] + a1 * w1s[64 + c + 3] + a2 * w1s[128 + c + 3];
            y4[c4] = o;
        }
    }
    __syncthreads();
    // fused BN statistics: re-read the block's tile (L2-hot)
    {
        int c = tid & 63;
        int rg = tid >> 6;  // 0..3
        int base = blockIdx.x * 256 + rg * 64;
        float s = 0.f, q = 0.f;
#pragma unroll 4
        for (int i = 0; i < 64; i++) {
            int r = base + i;
            if (r < n) {
                float val = y[r * 64 + c];
                s += val;
                q = fmaf(val, val, q);
            }
        }
        atomicAdd(&sS[c], s);
        atomicAdd(&sQ[c], q);
    }
    __syncthreads();
    if (tid < 64) {
        atomicAdd(&gsum[tid], sS[tid]);
        atomicAdd(&gsq[tid], sQ[tid]);
    }
}

// compute scale/shift; zero pad channels; reset stats for the next layer
__global__ void bn_final_kernel(float* gsum, float* gsq,
                                const float* __restrict__ gamma, const float* __restrict__ beta,
                                float* scale, float* shift, int n, int C) {
    int c = threadIdx.x;  // 128
    float sc = 0.f, sh = 0.f;
    if (c < C) {
        float inv_n = 1.0f / (float)n;
        float m = gsum[c] * inv_n;
        float var = gsq[c] * inv_n - m * m;
        float rs = rsqrtf(var + 1e-5f);
        sc = gamma[c] * rs;
        sh = beta[c] - m * sc;
    }
    scale[c] = sc;
    shift[c] = sh;
    gsum[c] = 0.f;
    gsq[c] = 0.f;
}

// ---------------- pull-aggregate with fused BN+relu on the source ----------------
__device__ __forceinline__ float4 bn4(float4 v, float4 sc, float4 sh) {
    float4 r;
    r.x = fmaxf(fmaf(v.x, sc.x, sh.x), 0.f);
    r.y = fmaxf(fmaf(v.y, sc.y, sh.y), 0.f);
    r.z = fmaxf(fmaf(v.z, sc.z, sh.z), 0.f);
    r.w = fmaxf(fmaf(v.w, sc.w, sh.w), 0.f);
    return r;
}

__device__ __forceinline__ void fma4(float4& acc, float nn, const float4& v) {
    acc.x = fmaf(nn, v.x, acc.x);
    acc.y = fmaf(nn, v.y, acc.y);
    acc.z = fmaf(nn, v.z, acc.z);
    acc.w = fmaf(nn, v.w, acc.w);
}

// layer-2 variant: ld4=16, G=8 lanes x 2 float4 each
__global__ void pull_bn64_kernel(const float* __restrict__ x, float* __restrict__ agg,
                                 const float* __restrict__ dinv,
                                 const int* __restrict__ rowptr, const int* __restrict__ srcs,
                                 const float* __restrict__ scale, const float* __restrict__ shift,
                                 int n) {
    int group = (blockIdx.x * blockDim.x + threadIdx.x) >> 3;
    int lane = threadIdx.x & 7;
    if (group >= n) return;
    const float4* sc4 = (const float4*)scale;
    const float4* sh4 = (const float4*)shift;
    float4 sc0 = sc4[lane], sc1 = sc4[lane + 8];
    float4 sh0 = sh4[lane], sh1 = sh4[lane + 8];
    float di = dinv[group];
    const float4* x4 = (const float4*)x;
    int b = group * 16 + lane;
    float dd = di * di;
    float4 t0 = bn4(__ldg(&x4[b]), sc0, sh0);
    float4 t1 = bn4(__ldg(&x4[b + 8]), sc1, sh1);
    float4 acc0 = make_float4(dd * t0.x, dd * t0.y, dd * t0.z, dd * t0.w);
    float4 acc1 = make_float4(dd * t1.x, dd * t1.y, dd * t1.z, dd * t1.w);
    int e = rowptr[group];
    int e1 = rowptr[group + 1];
    for (; e + 1 < e1; e += 2) {
        int s0 = __ldg(&srcs[e]);
        int s1 = __ldg(&srcs[e + 1]);
        float n0 = di * __ldg(&dinv[s0]);
        float n1 = di * __ldg(&dinv[s1]);
        int p0 = s0 * 16 + lane, p1 = s1 * 16 + lane;
        float4 u0 = __ldg(&x4[p0]);
        float4 u1 = __ldg(&x4[p0 + 8]);
        float4 v0 = __ldg(&x4[p1]);
        float4 v1 = __ldg(&x4[p1 + 8]);
        fma4(acc0, n0, bn4(u0, sc0, sh0));
        fma4(acc1, n0, bn4(u1, sc1, sh1));
        fma4(acc0, n1, bn4(v0, sc0, sh0));
        fma4(acc1, n1, bn4(v1, sc1, sh1));
    }
    if (e < e1) {
        int s0 = __ldg(&srcs[e]);
        float n0 = di * __ldg(&dinv[s0]);
        int p0 = s0 * 16 + lane;
        fma4(acc0, n0, bn4(__ldg(&x4[p0]), sc0, sh0));
        fma4(acc1, n0, bn4(__ldg(&x4[p0 + 8]), sc1, sh1));
    }
    float4* o4 = (float4*)agg;
    o4[b] = acc0;
    o4[b + 8] = acc1;
}

// layer-3 variant: ld4=24, G=8 lanes x 3 float4 each
__global__ void pull_bn96_kernel(const float* __restrict__ x, float* __restrict__ agg,
                                 const float* __restrict__ dinv,
                                 const int* __restrict__ rowptr, const int* __restrict__ srcs,
                                 const float* __restrict__ scale, const float* __restrict__ shift,
                                 int n) {
    int group = (blockIdx.x * blockDim.x + threadIdx.x) >> 3;
    int lane = threadIdx.x & 7;
    if (group >= n) return;
    const float4* sc4 = (const float4*)scale;
    const float4* sh4 = (const float4*)shift;
    float4 sc0 = sc4[lane], sc1 = sc4[lane + 8], sc2 = sc4[lane + 16];
    float4 sh0 = sh4[lane], sh1 = sh4[lane + 8], sh2 = sh4[lane + 16];
    float di = dinv[group];
    const float4* x4 = (const float4*)x;
    int b = group * 24 + lane;
    float dd = di * di;
    float4 t0 = bn4(__ldg(&x4[b]), sc0, sh0);
    float4 t1 = bn4(__ldg(&x4[b + 8]), sc1, sh1);
    float4 t2 = bn4(__ldg(&x4[b + 16]), sc2, sh2);
    float4 acc0 = make_float4(dd * t0.x, dd * t0.y, dd * t0.z, dd * t0.w);
    float4 acc1 = make_float4(dd * t1.x, dd * t1.y, dd * t1.z, dd * t1.w);
    float4 acc2 = make_float4(dd * t2.x, dd * t2.y, dd * t2.z, dd * t2.w);
    int e = rowptr[group];
    int e1 = rowptr[group + 1];
    for (; e + 1 < e1; e += 2) {
        int s0 = __ldg(&srcs[e]);
        int s1 = __ldg(&srcs[e + 1]);
        float n0 = di * __ldg(&dinv[s0]);
        float n1 = di * __ldg(&dinv[s1]);
        int p0 = s0 * 24 + lane, p1 = s1 * 24 + lane;
        float4 u0 = __ldg(&x4[p0]);
        float4 u1 = __ldg(&x4[p0 + 8]);
        float4 u2 = __ldg(&x4[p0 + 16]);
        float4 v0 = __ldg(&x4[p1]);
        float4 v1 = __ldg(&x4[p1 + 8]);
        float4 v2 = __ldg(&x4[p1 + 16]);
        fma4(acc0, n0, bn4(u0, sc0, sh0));
        fma4(acc1, n0, bn4(u1, sc1, sh1));
        fma4(acc2, n0, bn4(u2, sc2, sh2));
        fma4(acc0, n1, bn4(v0, sc0, sh0));
        fma4(acc1, n1, bn4(v1, sc1, sh1));
        fma4(acc2, n1, bn4(v2, sc2, sh2));
    }
    if (e < e1) {
        int s0 = __ldg(&srcs[e]);
        float n0 = di * __ldg(&dinv[s0]);
        int p0 = s0 * 24 + lane;
        fma4(acc0, n0, bn4(__ldg(&x4[p0]), sc0, sh0));
        fma4(acc1, n0, bn4(__ldg(&x4[p0 + 8]), sc1, sh1));
        fma4(acc2, n0, bn4(__ldg(&x4[p0 + 16]), sc2, sh2));
    }
    float4* o4 = (float4*)agg;
    o4[b] = acc0;
    o4[b + 8] = acc1;
    o4[b + 16] = acc2;
}

// ---------------- tf32 tensor-core GEMM (R7-proven staging) ----------------
__device__ __forceinline__ unsigned f2tf32(float v) {
    unsigned u;
    asm("cvt.rna.tf32.f32 %0, %1;" : "=r"(u) : "f"(v));
    return u;
}

#define MMA_TF32(d, A, B)                                              \
    asm volatile(                                                      \
        "mma.sync.aligned.m16n8k8.row.col.f32.tf32.tf32.f32 "          \
        "{%0,%1,%2,%3}, {%4,%5,%6,%7}, {%8,%9}, {%0,%1,%2,%3};"        \
        : "+f"(d[0]), "+f"(d[1]), "+f"(d[2]), "+f"(d[3])               \
        : "r"(A.x), "r"(A.y), "r"(A.z), "r"(A.w), "r"(B.x), "r"(B.y))

template <int NT, int DOPOOL>  // NT: n8-tiles per warp (3->96 cols, 4->128 cols)
__global__ __launch_bounds__(256) void gemm_tf32_kernel(
    const float* __restrict__ X, const float* __restrict__ W,
    const float* __restrict__ bias, float* __restrict__ Y,
    int n, int K, int M, int ldX, int ldY, int doRelu,
    const float* __restrict__ bnScale, const float* __restrict__ bnShift,
    float* gsum, float* gsq,
    const int* __restrict__ batch, float* pooled) {
    const int COLS = NT * 32;
    __shared__ unsigned Xfrag[4 * 8 * 32 * 4];   // [ks][mt][lane][4]
    __shared__ unsigned Wfrag[4 * 16 * 32 * 2];  // [ks][ntGlobal][lane][2]
    __shared__ float sSum[DOPOOL ? 1 : 128], sSq[DOPOOL ? 1 : 128];
    __shared__ float spool[DOPOOL ? 16 * 128 : 1];

    int tid = threadIdx.x;
    int lane = tid & 31;
    int wid = tid >> 5;
    int warpM = wid >> 2;  // 0..1
    int warpN = wid & 3;   // 0..3
    int row0 = blockIdx.x * 128;
    int g = lane >> 2, tig = lane & 3;

    float acc[4][NT][4];
#pragma unroll
    for (int mt = 0; mt < 4; mt++)
#pragma unroll
        for (int nt = 0; nt < NT; nt++)
#pragma unroll
            for (int r = 0; r < 4; r++) acc[mt][nt][r] = 0.f;

    if (!DOPOOL) {
        if (gsum && tid < 128) { sSum[tid] = 0.f; sSq[tid] = 0.f; }
    } else {
        for (int i = tid; i < 16 * 128; i += 256) spool[i] = 0.f;
    }

    for (int k0 = 0; k0 < K; k0 += 32) {
        __syncthreads();
        // stage X fragments (optionally applying BN+relu to X)
        for (int t = tid; t < 128 * 32; t += 256) {
            int row = t >> 5, kk = t & 31;
            int gr = row0 + row, kg = k0 + kk;
            float v = 0.f;
            if (gr < n && kg < K) {
                v = X[gr * ldX + kg];
                if (bnScale) v = fmaxf(fmaf(v, bnScale[kg], bnShift[kg]), 0.f);
            }
            int mt = row >> 4, r16 = row & 15;
            int gg = r16 & 7, regRow = r16 >> 3;
            int tt = kk & 3, ks = kk >> 3, j = (kk >> 2) & 1;
            Xfrag[(((ks << 3) + mt) << 7) + ((gg << 2) + tt) * 4 + regRow + 2 * j] = f2tf32(v);
        }
        // stage W fragments
        for (int t = tid; t < 32 * COLS; t += 256) {
            int kk = t / COLS, cc = t - kk * COLS;
            int kg = k0 + kk;
            float v = (kg < K && cc < M) ? W[kg * M + cc] : 0.f;
            int tt = kk & 3, ks = kk >> 3, j = (kk >> 2) & 1;
            int nt = cc >> 3, gn = cc & 7;
            Wfrag[(((ks << 4) + nt) << 6) + ((gn << 2) + tt) * 2 + j] = f2tf32(v);
        }
        __syncthreads();
#pragma unroll
        for (int ks = 0; ks < 4; ks++) {
            uint4 a[4];
            uint2 b[NT];
#pragma unroll
            for (int mt = 0; mt < 4; mt++)
                a[mt] = *(const uint4*)&Xfrag[(((ks << 3) + (warpM << 2) + mt) << 7) + (lane << 2)];
#pragma unroll
            for (int nt = 0; nt < NT; nt++)
                b[nt] = *(const uint2*)&Wfrag[(((ks << 4) + warpN * NT + nt) << 6) + (lane << 1)];
#pragma unroll
            for (int mt = 0; mt < 4; mt++)
#pragma unroll
                for (int nt = 0; nt < NT; nt++) MMA_TF32(acc[mt][nt], a[mt], b[nt]);
        }
    }

    if (!DOPOOL) {
        // fused BN statistics (pre-activation); padded rows/cols are exact zeros
        if (gsum) {
#pragma unroll
            for (int nt = 0; nt < NT; nt++) {
                int cb = (warpN * NT + nt) * 8 + tig * 2;
                float s0 = 0.f, q0 = 0.f, s1 = 0.f, q1 = 0.f;
#pragma unroll
                for (int mt = 0; mt < 4; mt++) {
                    float v0 = acc[mt][nt][0], v2 = acc[mt][nt][2];
                    float v1 = acc[mt][nt][1], v3 = acc[mt][nt][3];
                    s0 += v0 + v2; q0 += v0 * v0 + v2 * v2;
                    s1 += v1 + v3; q1 += v1 * v1 + v3 * v3;
                }
                atomicAdd(&sSum[cb], s0);
                atomicAdd(&sSq[cb], q0);
                atomicAdd(&sSum[cb + 1], s1);
                atomicAdd(&sSq[cb + 1], q1);
            }
            __syncthreads();
            if (tid < 128) {
                atomicAdd(&gsum[tid], sSum[tid]);
                atomicAdd(&gsq[tid], sSq[tid]);
            }
        }
        // store
#pragma unroll
        for (int mt = 0; mt < 4; mt++) {
            int rbase = row0 + warpM * 64 + mt * 16 + g;
#pragma unroll
            for (int nt = 0; nt < NT; nt++) {
                int cb = (warpN * NT + nt) * 8 + tig * 2;
                if (cb >= ldY) continue;
                float bb0 = 0.f, bb1 = 0.f;
                if (bias) {
                    if (cb < M) bb0 = bias[cb];
                    if (cb + 1 < M) bb1 = bias[cb + 1];
                }
#pragma unroll
                for (int h = 0; h < 2; h++) {
                    int r = rbase + h * 8;
                    if (r >= n) continue;
                    float v0 = acc[mt][nt][2 * h] + bb0;
                    float v1 = acc[mt][nt][2 * h + 1] + bb1;
                    if (doRelu) { v0 = fmaxf(v0, 0.f); v1 = fmaxf(v1, 0.f); }
                    if (cb >= M) v0 = 0.f;      // pad column -> keep zero
                    if (cb + 1 >= M) v1 = 0.f;
                    *(float2*)&Y[r * ldY + cb] = make_float2(v0, v1);
                }
            }
        }
    } else {
        // fused global-sum-pool: relu(v + bias) accumulated per graph
#pragma unroll
        for (int mt = 0; mt < 4; mt++) {
            int rbase = row0 + warpM * 64 + mt * 16 + g;
#pragma unroll
            for (int nt = 0; nt < NT; nt++) {
                int cb = (warpN * NT + nt) * 8 + tig * 2;
                float bb0 = (cb < M) ? bias[cb] : 0.f;
                float bb1 = (cb + 1 < M) ? bias[cb + 1] : 0.f;
#pragma unroll
                for (int h = 0; h < 2; h++) {
                    int r = rbase + h * 8;
                    if (r >= n) continue;
                    int gb = __ldg(&batch[r]);
                    float v0 = fmaxf(acc[mt][nt][2 * h] + bb0, 0.f);
                    float v1 = fmaxf(acc[mt][nt][2 * h + 1] + bb1, 0.f);
                    atomicAdd(&spool[gb * 128 + cb], v0);
                    atomicAdd(&spool[gb * 128 + cb + 1], v1);
                }
            }
        }
        __syncthreads();
        int rlast = min(row0 + 127, n - 1);
        if (row0 < n) {
            int gmin = __ldg(&batch[row0]);
            int gmax = __ldg(&batch[rlast]);
            if (tid < 128) {
                for (int gg2 = gmin; gg2 <= gmax; gg2++)
                    atomicAdd(&pooled[gg2 * 128 + tid], spool[gg2 * 128 + tid]);
            }
        }
    }
}

// ---------------- MLP head on [16,128] ----------------
__global__ void head_kernel(const float* __restrict__ pooled,
                            const float* __restrict__ fw1, const float* __restrict__ fb1,
                            const float* __restrict__ fw2, const float* __restrict__ fb2,
                            const float* __restrict__ fw3, const float* __restrict__ fb3,
                            float* __restrict__ out) {
    __shared__ float s0[128], s1[128], s2[128];
    int t = threadIdx.x;
    int g = blockIdx.x;
    s0[t] = pooled[g * 128 + t];
    __syncthreads();
    float a = fb1[t];
    for (int k = 0; k < 128; k++) a = fmaf(s0[k], fw1[k * 128 + t], a);
    s1[t] = fmaxf(a, 0.f);
    __syncthreads();
    a = fb2[t];
    for (int k = 0; k < 128; k++) a = fmaf(s1[k], fw2[k * 128 + t], a);
    s2[t] = fmaxf(a, 0.f);
    __syncthreads();
    if (t < 100) {
        a = fb3[t];
        for (int k = 0; k < 128; k++) a = fmaf(s2[k], fw3[k * 100 + t], a);
        out[g * 100 + t] = a;
    }
}

// ---------------- launcher ----------------
extern "C" void kernel_launch(void* const* d_in, const int* in_sizes, int n_in,
                              void* d_out, int out_size) {
    const float* pos = (const float*)d_in[0];
    const int* ei = (const int*)d_in[1];     // int32
    const int* batch = (const int*)d_in[2];  // int32
    const float* w1 = (const float*)d_in[3];
    // d_in[4] = b1: cancels in BatchNorm (mean subtraction) -> skipped
    const float* g1 = (const float*)d_in[5];
    const float* be1 = (const float*)d_in[6];
    const float* w2 = (const float*)d_in[7];
    const float* g2 = (const float*)d_in[9];
    const float* be2 = (const float*)d_in[10];
    const float* w3 = (const float*)d_in[11];
    const float* g3 = (const float*)d_in[13];
    const float* be3 = (const float*)d_in[14];
    const float* fw0 = (const float*)d_in[15];
    const float* fb0 = (const float*)d_in[16];
    const float* fw1 = (const float*)d_in[17];
    const float* fb1 = (const float*)d_in[18];
    const float* fw2 = (const float*)d_in[19];
    const float* fb2 = (const float*)d_in[20];
    const float* fw3 = (const float*)d_in[21];
    const float* fb3 = (const float*)d_in[22];

    int n = in_sizes[2];       // N
    int E = in_sizes[1] / 2;   // directed edges
    const int* src = ei;
    const int* dst = ei + E;

    float *A, *B, *dinv, *stats, *scale, *shift, *pooled;
    int *cnt, *rowptr, *cursor, *srcs, *bsum;
    cudaGetSymbolAddress((void**)&A, g_bufA);
    cudaGetSymbolAddress((void**)&B, g_bufB);
    cudaGetSymbolAddress((void**)&dinv, g_dinv);
    cudaGetSymbolAddress((void**)&stats, g_stats);
    cudaGetSymbolAddress((void**)&scale, g_scale);
    cudaGetSymbolAddress((void**)&shift, g_shift);
    cudaGetSymbolAddress((void**)&pooled, g_pool);
    cudaGetSymbolAddress((void**)&cnt, g_cnt);
    cudaGetSymbolAddress((void**)&rowptr, g_rowptr);
    cudaGetSymbolAddress((void**)&cursor, g_cursor);
    cudaGetSymbolAddress((void**)&srcs, g_srcs);
    cudaGetSymbolAddress((void**)&bsum, g_bsum);
    float* gsum = stats;
    float* gsq = stats + 128;

    const int T = 256;
    int nb = ceil_div(n, 256);
    int gemmBlocks = ceil_div(n, 128);

    // ---- setup + CSR build ----
    setup_kernel<<<ceil_div(n, T), T>>>(cnt, stats, pooled, n);
    hist_kernel<<<ceil_div(E, T), T>>>(cnt, dst, E);
    scan1_kernel<<<nb, 256>>>(cnt, rowptr, bsum, n);
    scan3_kernel<<<nb, 512>>>(rowptr, bsum, cursor, cnt, dinv, n, E, nb);
    reorder_kernel<<<ceil_div(E, T), T>>>(src, dst, cursor, srcs, E);

    // ---- layer 1: pull(C=3) + GEMM 3->64 + BN stats fused -> B (pre-BN); final ----
    pull3_k3_kernel<<<ceil_div(n, T), T>>>(pos, w1, dinv, rowptr, srcs, B, n, gsum, gsq);
    bn_final_kernel<<<1, 128>>>(gsum, gsq, g1, be1, scale, shift, n, 64);

    // ---- layer 2: pull(BN1 fused, G=8x2) -> A [n,64]; tf32 GEMM 64->94 -> B + stats ----
    pull_bn64_kernel<<<ceil_div(n * 8, T), T>>>(B, A, dinv, rowptr, srcs, scale, shift, n);
    gemm_tf32_kernel<3, 0><<<gemmBlocks, 256>>>(A, w2, nullptr, B, n, 64, 94, 64, 96, 0,
                                                nullptr, nullptr, gsum, gsq,
                                                nullptr, nullptr);
    bn_final_kernel<<<1, 128>>>(gsum, gsq, g2, be2, scale, shift, n, 94);

    // ---- layer 3: pull(BN2 fused, G=8x3) -> A [n,96]; tf32 GEMM 94->128 -> B + stats ----
    pull_bn96_kernel<<<ceil_div(n * 8, T), T>>>(B, A, dinv, rowptr, srcs, scale, shift, n);
    gemm_tf32_kernel<4, 0><<<gemmBlocks, 256>>>(A, w3, nullptr, B, n, 94, 128, 96, 128, 0,
                                                nullptr, nullptr, gsum, gsq,
                                                nullptr, nullptr);
    bn_final_kernel<<<1, 128>>>(gsum, gsq, g3, be3, scale, shift, n, 128);

    // ---- fw0: BN3+relu fused into X staging; +bias +relu; pool fused -> pooled ----
    gemm_tf32_kernel<4, 1><<<gemmBlocks, 256>>>(B, fw0, fb0, nullptr, n, 128, 128, 128, 128, 1,
                                                scale, shift, nullptr, nullptr,
                                                batch, pooled);

    // ---- head ----
    head_kernel<<<16, 128>>>(pooled, fw1, fb1, fw2, fb2, fw3, fb3, (float*)d_out);
}